// round 1
// baseline (speedup 1.0000x reference)
#include <cuda_runtime.h>
#include <math.h>

#define BB 8
#define CC 4
#define HH 96
#define WW 96
#define HW_ (HH*WW)
#define NC 3                 // classes 1..3 (class 0 ignored)
#define NBIN 18051           // squared distances 0..95^2+95^2
#define NPAIR (BB*NC)        // 24
#define NHIST (NPAIR*2)      // 48 (fwd, rev)
#define INF_ROW 1000000000

// ---------------- device scratch (no allocations allowed) ----------------
__device__ unsigned char g_pred[BB*HW_];                 // argmax class per pixel
__device__ int           g_row[2][BB][NC][HH][WW];       // per-row 1D squared dist (m=0: pred mask A, m=1: label mask B)
__device__ unsigned int  g_hist[NHIST][NBIN];            // histograms of squared EDT over masked pixels
__device__ float         g_fr[BB][NC][2];                // percentile result: [.,.,0]=fwd, [.,.,1]=rev

// ---------------- kernel 0: clear histograms (graph replays accumulate otherwise) ----
__global__ void k_zero() {
    int i = blockIdx.x * blockDim.x + threadIdx.x;
    if (i < NHIST * NBIN) ((unsigned int*)g_hist)[i] = 0u;
}

// ---------------- kernel 1: argmax over channels (softmax is monotone) ----------------
__global__ void k_argmax(const float* __restrict__ pred) {
    int i = blockIdx.x * blockDim.x + threadIdx.x;
    if (i >= BB * HW_) return;
    int b = i / HW_, pix = i - b * HW_;
    const float* p = pred + (size_t)b * CC * HW_ + pix;
    float best = p[0];
    int bi = 0;
#pragma unroll
    for (int c = 1; c < CC; c++) {
        float v = p[(size_t)c * HW_];
        if (v > best) { best = v; bi = c; }   // first-occurrence argmax (strict >)
    }
    g_pred[i] = (unsigned char)bi;
}

// ---------------- kernel 2: per-row 1D squared nearest distance ----------------
// One thread per (mask, b, c, row): left scan + right scan.
__global__ void k_rowdist(const int* __restrict__ labels) {
    int t = blockIdx.x * blockDim.x + threadIdx.x;
    if (t >= 2 * BB * NC * HH) return;
    int y = t % HH; int r = t / HH;
    int c = r % NC + 1; r /= NC;
    int b = r % BB; int m = r / BB;   // m=0 -> pred mask (A), m=1 -> label mask (B)

    unsigned int bits[3] = {0u, 0u, 0u};
    if (m == 0) {
        const unsigned char* pr = g_pred + b * HW_ + y * WW;
        for (int x = 0; x < WW; x++) if (pr[x] == c) bits[x >> 5] |= (1u << (x & 31));
    } else {
        const int* lb = labels + b * HW_ + y * WW;
        for (int x = 0; x < WW; x++) if (lb[x] == c) bits[x >> 5] |= (1u << (x & 31));
    }

    int* out = &g_row[m][b][c - 1][y][0];
    int d = 1 << 20;
    for (int x = 0; x < WW; x++) {
        d = ((bits[x >> 5] >> (x & 31)) & 1u) ? 0 : d + 1;
        out[x] = d;                                  // temp: left distance
    }
    d = 1 << 20;
    for (int x = WW - 1; x >= 0; x--) {
        d = ((bits[x >> 5] >> (x & 31)) & 1u) ? 0 : d + 1;
        int dm = min(out[x], d);
        out[x] = (dm >= WW) ? INF_ROW : dm * dm;     // final: squared 1D distance (or INF if row empty)
    }
}

// ---------------- kernel 3: EDT query (early-exit radial scan) + histogram ----------------
__device__ __forceinline__ int edt2_query(const int* __restrict__ fcol, int y) {
    // fcol points at column x of the row-distance array; stride WW between rows.
    int e = fcol[y * WW];
#pragma unroll 4
    for (int rr = 1; rr < HH; rr++) {
        int r2 = rr * rr;
        if (r2 >= e) break;                          // no farther row can improve
        int up = y - rr, dn = y + rr;
        if (up >= 0) e = min(e, r2 + fcol[up * WW]);
        if (dn < HH) e = min(e, r2 + fcol[dn * WW]);
    }
    return e;
}

__global__ void k_hist(const int* __restrict__ labels) {
    int pair = blockIdx.y;                           // 0..23
    int c = pair % NC + 1, b = pair / NC;
    int pix = blockIdx.x * blockDim.x + threadIdx.x;
    if (pix >= HW_) return;
    int y = pix / WW, x = pix - y * WW;

    bool ma = (g_pred[b * HW_ + pix] == c);
    bool mb = (labels[b * HW_ + pix] == c);
    if (!ma && !mb) return;

    if (ma) {   // fwd: distance from A pixel to nearest B pixel = EDT of mask B
        int e = edt2_query(&g_row[1][b][c - 1][0][x], y);
        atomicAdd(&g_hist[pair * 2][min(e, NBIN - 1)], 1u);
    }
    if (mb) {   // rev: distance from B pixel to nearest A pixel = EDT of mask A
        int e = edt2_query(&g_row[0][b][c - 1][0][x], y);
        atomicAdd(&g_hist[pair * 2 + 1][min(e, NBIN - 1)], 1u);
    }
}

// ---------------- kernel 4: masked percentile from histogram ----------------
// One block per histogram. Matches jnp._masked_percentile exactly in fp32.
__global__ void k_pct() {
    int hid = blockIdx.x;
    const unsigned int* h = g_hist[hid];
    __shared__ unsigned int psum[257];
    __shared__ int bin_lo, bin_hi;
    int t = threadIdx.x;
    const int CH = (NBIN + 255) / 256;               // 71 bins per thread
    int s0 = t * CH;
    int s1 = min(s0 + CH, NBIN);

    unsigned int sum = 0;
    for (int i = s0; i < s1; i++) sum += h[i];
    psum[t] = sum;
    __syncthreads();
    if (t == 0) {
        unsigned int acc = 0;
        for (int i = 0; i < 256; i++) { unsigned int v = psum[i]; psum[i] = acc; acc += v; }
        psum[256] = acc;
    }
    __syncthreads();

    unsigned int n = psum[256];
    int nm1 = (int)n - 1; if (nm1 < 0) nm1 = 0;
    float pos = 0.95f * (float)nm1;                  // fp32, same as jnp
    int lo = (int)floorf(pos), hi = (int)ceilf(pos);
    float frac = pos - (float)lo;

    if (n > 0) {
        unsigned int base = psum[t], myend = psum[t + 1];
        if ((unsigned int)lo >= base && (unsigned int)lo < myend) {
            unsigned int acc = base;
            for (int i = s0; i < NBIN; i++) { acc += h[i]; if (acc > (unsigned int)lo) { bin_lo = i; break; } }
        }
        if ((unsigned int)hi >= base && (unsigned int)hi < myend) {
            unsigned int acc = base;
            for (int i = s0; i < NBIN; i++) { acc += h[i]; if (acc > (unsigned int)hi) { bin_hi = i; break; } }
        }
    }
    __syncthreads();

    if (t == 0) {
        float val;
        if (n == 0) {
            val = __int_as_float(0x7f800000);        // +inf, matches s[0]=inf
        } else {
            float slo = sqrtf((float)bin_lo);
            float shi = sqrtf((float)bin_hi);
            val = slo * (1.0f - frac) + shi * frac;
        }
        int pair = hid >> 1, dir = hid & 1;
        g_fr[pair / NC][pair % NC][dir] = val;
    }
}

// ---------------- kernel 5: batch means + finalize -> 18 outputs ----------------
__global__ void k_final(float* __restrict__ out) {
    if (threadIdx.x != 0) return;
    float F[CC], R[CC], M[CC];
    F[0] = R[0] = M[0] = 0.0f;                       // class 0 zeroed (IGNORE)
    for (int c = 1; c < CC; c++) {
        float sf = 0.f, sr = 0.f, sm = 0.f;
        for (int b = 0; b < BB; b++) {
            float f = g_fr[b][c - 1][0];
            float r = g_fr[b][c - 1][1];
            sf += f; sr += r; sm += fmaxf(f, r);
        }
        F[c] = sf / (float)BB; R[c] = sr / (float)BB; M[c] = sm / (float)BB;
    }
    const float* vs[3] = { M, F, R };                // output order: MHD, FHD, RHD
    for (int k = 0; k < 3; k++) {
        const float* v = vs[k];
        float s = 0.f, s1 = 0.f;
        for (int c = 0; c < CC; c++) {
            out[k * 6 + c] = v[c];
            s += v[c];
            if (c >= 1) s1 += v[c];
        }
        out[k * 6 + 4] = s / (float)CC;
        out[k * 6 + 5] = s1 / (float)(CC - 1);
    }
}

// ---------------- launch ----------------
extern "C" void kernel_launch(void* const* d_in, const int* in_sizes, int n_in,
                              void* d_out, int out_size) {
    const float* pred   = (const float*)d_in[0];
    const int*   labels = (const int*)d_in[1];
    float*       out    = (float*)d_out;

    k_zero   <<<(NHIST * NBIN + 255) / 256, 256>>>();
    k_argmax <<<(BB * HW_ + 255) / 256, 256>>>(pred);
    k_rowdist<<<(2 * BB * NC * HH + 127) / 128, 128>>>(labels);
    dim3 g((HW_ + 255) / 256, NPAIR);
    k_hist   <<<g, 256>>>(labels);
    k_pct    <<<NHIST, 256>>>();
    k_final  <<<1, 32>>>(out);
}